// round 10
// baseline (speedup 1.0000x reference)
#include <cuda_runtime.h>
#include <cstdint>

#define C_DIM 256
#define K_DIM 1024
#define HW    1024
#define TM    64
#define TN    128
#define CCH   16
#define NSTAGE 128        // 8 kc * 16 cc
#define NTHREADS 256

// ---------------- device globals (scratch; no runtime allocation) ----------------
__device__ __align__(16) float  g_embT[C_DIM * K_DIM];  // emb transposed: [c][k]
__device__ __align__(16) float  g_esq[K_DIM];           // ||e_k||^2 (ref fp32 bits)
__device__ __align__(16) float  g_zsq[64 * HW];         // ||z_n||^2 (ref fp32 bits)
__device__ double g_sumsq;
__device__ double g_sumlin;

// ---------------- tiny helper kernels ----------------
__global__ void vq_zero_kernel() { g_sumsq = 0.0; g_sumlin = 0.0; }

// emb [K][C] -> g_embT [C][K], classic 32x32 smem transpose
__global__ void vq_transpose_kernel(const float* __restrict__ emb) {
    __shared__ float t[32][33];
    int k0 = blockIdx.x * 32, c0 = blockIdx.y * 32;
    int tx = threadIdx.x, ty = threadIdx.y;
#pragma unroll
    for (int r = ty; r < 32; r += 8)
        t[r][tx] = emb[(size_t)(k0 + r) * C_DIM + c0 + tx];
    __syncthreads();
#pragma unroll
    for (int r = ty; r < 32; r += 8)
        g_embT[(size_t)(c0 + r) * K_DIM + k0 + tx] = t[tx][r];
}

// ||e_k||^2: warp loads row coalesced into smem, lane 0 does the bit-exact
// sequential fp32 reduce (mul/add separately rounded, c ascending).
__global__ void vq_esq_kernel(const float* __restrict__ emb) {
    __shared__ float row_s[8][C_DIM];
    int w = threadIdx.x >> 5, lane = threadIdx.x & 31;
    int k = blockIdx.x * 8 + w;
    const float* row = emb + (size_t)k * C_DIM;
#pragma unroll
    for (int r = 0; r < 8; r++) row_s[w][lane + 32 * r] = row[lane + 32 * r];
    __syncwarp();
    if (lane == 0) {
        float acc = 0.0f;
#pragma unroll 8
        for (int c = 0; c < C_DIM; c++) {
            float v = row_s[w][c];
            acc = __fadd_rn(acc, __fmul_rn(v, v));
        }
        g_esq[k] = acc;
    }
}

// ||z_n||^2: STRICT sequential fp32 over c ascending (coalesced across tokens)
__global__ void vq_zsq_kernel(const float* __restrict__ z) {
    int n = blockIdx.x * blockDim.x + threadIdx.x;
    int b = n >> 10, s = n & (HW - 1);
    const float* base = z + ((size_t)b * C_DIM) * HW + s;
    float acc = 0.0f;
#pragma unroll 8
    for (int c = 0; c < C_DIM; c++) {
        float v = base[(size_t)c * HW];
        acc = __fadd_rn(acc, __fmul_rn(v, v));
    }
    g_zsq[n] = acc;
}

// ---------------- packed f32x2 helpers ----------------
__device__ __forceinline__ void fma2(unsigned long long& d,
                                     unsigned long long a,
                                     unsigned long long b) {
    asm("fma.rn.f32x2 %0, %1, %2, %0;" : "+l"(d) : "l"(a), "l"(b));
}
__device__ __forceinline__ void unpack2(unsigned long long v, float& lo, float& hi) {
    unsigned int l, h;
    asm("mov.b64 {%0, %1}, %2;" : "=r"(l), "=r"(h) : "l"(v));
    lo = __uint_as_float(l);
    hi = __uint_as_float(h);
}
// Emulate reference fp32 chain: d = fl( fl(zsq + esq) - fl(2*ez) )
__device__ __forceinline__ float ref_dist(float zsq, float esq, float ez) {
    float t = __fadd_rn(zsq, esq);
    return __fadd_rn(t, __fmul_rn(-2.0f, ez));
}

// ---------------- main kernel ----------------
// 64 tokens x 1024 codes per CTA, 256 thr, 2 CTAs/SM.
// z_tile fp32 [256 c][64 tok] (64KB). E staged in 16-c chunks of 128 codes,
// PRE-DUPLICATED into f32x2 (each code stored as (e,e)), double-buffered,
// software-pipelined LDG two stages ahead. Inner loop: zero splat MOVs —
// z loaded as natural token-pairs (LDS.128 = 2 f32x2), e as dup'd pairs.
// Accumulation per (token, code): single fused-FMA chain over c ascending —
// bit-identical to the R5 passing kernel.
#define OFF_EBUF 65536u
#define OFF_INDS (65536u + 32768u)
#define OFF_RED  (OFF_INDS + 256u)
#define SMEM_BYTES (OFF_RED + 64u)

__global__ __launch_bounds__(NTHREADS, 2)
void vq_main_kernel(const float* __restrict__ z, const float* __restrict__ emb,
                    float* __restrict__ out) {
    extern __shared__ char smem[];
    float* z_tile = (float*)smem;                                  // [256][64]
    unsigned long long* ebuf = (unsigned long long*)(smem + OFF_EBUF); // [2][16*128]
    int*   s_inds = (int*)(smem + OFF_INDS);                       // [64]
    float* s_red  = (float*)(smem + OFF_RED);                      // [16]

    const int tid = threadIdx.x;
    const int tx = tid & 15;   // code group: codes tx*4..+3 and 64+tx*4..+3 (per kc)
    const int ty = tid >> 4;   // token group: tokens ty*4..+3
    const int blk = blockIdx.x;
    const int b  = blk >> 4;
    const int s0 = (blk & 15) * TM;
    const float* zb = z + ((size_t)b * C_DIM) * HW + s0;

    // load z tile: z_tile[c][i] = z[b][c][s0+i] (fully coalesced)
#pragma unroll
    for (int r = 0; r < 16; r++) {
        int idx = tid + r * NTHREADS;
        int c = idx >> 4, i4 = idx & 15;
        *(float4*)&z_tile[c * TM + i4 * 4] =
            *(const float4*)(zb + (size_t)c * HW + i4 * 4);
    }

    float zs4[4];
#pragma unroll
    for (int t = 0; t < 4; t++)
        zs4[t] = g_zsq[b * HW + s0 + (ty << 2) + t];

    float bmin[4];
    int   bidx[4];
#pragma unroll
    for (int t = 0; t < 4; t++) { bmin[t] = 3.4e38f; bidx[t] = 0; }

    // ---- e staging: thread covers 8 codes of one c-row per chunk ----
    const int er = tid >> 4;     // c-row 0..15 within chunk
    const int eseg = tid & 15;   // 8-code segment 0..15

    float4 rp[2];                // prefetch registers (8 codes fp32)
    auto ldg_chunk = [&](int s) {
        int kc = s >> 4, cc = s & 15;
        const float* src = g_embT + (size_t)(cc * CCH + er) * K_DIM + kc * TN + eseg * 8;
        rp[0] = *(const float4*)(src);
        rp[1] = *(const float4*)(src + 4);
    };
    auto sts_chunk = [&](int buf) {
        float4* dst = (float4*)(ebuf + (size_t)buf * (CCH * TN) + er * TN + eseg * 8);
        dst[0] = make_float4(rp[0].x, rp[0].x, rp[0].y, rp[0].y);
        dst[1] = make_float4(rp[0].z, rp[0].z, rp[0].w, rp[0].w);
        dst[2] = make_float4(rp[1].x, rp[1].x, rp[1].y, rp[1].y);
        dst[3] = make_float4(rp[1].z, rp[1].z, rp[1].w, rp[1].w);
    };

    ldg_chunk(0);
    sts_chunk(0);
    ldg_chunk(1);
    __syncthreads();            // also covers z_tile visibility

    unsigned long long acc[2][8];   // [token-pair][code j]; lo=even tok, hi=odd tok

    for (int s = 0; s < NSTAGE; s++) {
        const int kc = s >> 4, cc = s & 15;
        if (cc == 0) {
#pragma unroll
            for (int p = 0; p < 2; p++)
#pragma unroll
                for (int j = 0; j < 8; j++) acc[p][j] = 0ull;
        }

        {   // compute: 16 c-iters on buf s&1
            const unsigned long long* eb = ebuf + (size_t)(s & 1) * (CCH * TN);
            const float* zr = z_tile + (cc * CCH) * TM + (ty << 2);
#pragma unroll
            for (int ci = 0; ci < CCH; ci++) {
                ulonglong2 zp = *(const ulonglong2*)(zr + ci * TM);      // 4 tokens = 2 f32x2
                const unsigned long long* e = eb + ci * TN + (tx << 2);
                ulonglong2 eA = *(const ulonglong2*)(e);                 // codes tx*4, +1 (dup)
                ulonglong2 eB = *(const ulonglong2*)(e + 2);             // codes tx*4+2, +3
                ulonglong2 eC = *(const ulonglong2*)(e + 64);            // codes 64+tx*4, +1
                ulonglong2 eD = *(const ulonglong2*)(e + 66);            // codes 64+tx*4+2, +3
                fma2(acc[0][0], zp.x, eA.x); fma2(acc[1][0], zp.y, eA.x);
                fma2(acc[0][1], zp.x, eA.y); fma2(acc[1][1], zp.y, eA.y);
                fma2(acc[0][2], zp.x, eB.x); fma2(acc[1][2], zp.y, eB.x);
                fma2(acc[0][3], zp.x, eB.y); fma2(acc[1][3], zp.y, eB.y);
                fma2(acc[0][4], zp.x, eC.x); fma2(acc[1][4], zp.y, eC.x);
                fma2(acc[0][5], zp.x, eC.y); fma2(acc[1][5], zp.y, eC.y);
                fma2(acc[0][6], zp.x, eD.x); fma2(acc[1][6], zp.y, eD.x);
                fma2(acc[0][7], zp.x, eD.y); fma2(acc[1][7], zp.y, eD.y);
            }
        }

        if (cc == 15) {     // kc epilogue: ref-emulated dists + running argmin
            const int kA = kc * TN + (tx << 2);
            const int kB = kA + 64;
            float4 eqA = *(const float4*)&g_esq[kA];
            float4 eqB = *(const float4*)&g_esq[kB];
#pragma unroll
            for (int t = 0; t < 4; t++) {
                const int p = t >> 1, h = t & 1;
                const float zs = zs4[t];
                float d[8];
#pragma unroll
                for (int j = 0; j < 8; j++) {
                    float lo, hi;
                    unpack2(acc[p][j], lo, hi);
                    float ez = h ? hi : lo;
                    float eq = (j < 4) ? ((j == 0) ? eqA.x : (j == 1) ? eqA.y : (j == 2) ? eqA.z : eqA.w)
                                       : ((j == 4) ? eqB.x : (j == 5) ? eqB.y : (j == 6) ? eqB.z : eqB.w);
                    d[j] = ref_dist(zs, eq, ez);
                }
                float bd = d[0]; int bk = kA;          // ascending k, strict <
                if (d[1] < bd) { bd = d[1]; bk = kA + 1; }
                if (d[2] < bd) { bd = d[2]; bk = kA + 2; }
                if (d[3] < bd) { bd = d[3]; bk = kA + 3; }
                if (d[4] < bd) { bd = d[4]; bk = kB;     }
                if (d[5] < bd) { bd = d[5]; bk = kB + 1; }
                if (d[6] < bd) { bd = d[6]; bk = kB + 2; }
                if (d[7] < bd) { bd = d[7]; bk = kB + 3; }
#pragma unroll
                for (int m = 8; m > 0; m >>= 1) {      // reduce over 16 tx lanes
                    float od = __shfl_xor_sync(0xffffffffu, bd, m);
                    int   ok = __shfl_xor_sync(0xffffffffu, bk, m);
                    if (od < bd || (od == bd && ok < bk)) { bd = od; bk = ok; }
                }
                if (bd < bmin[t]) { bmin[t] = bd; bidx[t] = bk; }  // earlier kc wins ties
            }
        }

        // pipeline: store chunk s+1 (regs loaded last stage), prefetch chunk s+2
        if (s + 1 < NSTAGE) sts_chunk((s + 1) & 1);
        if (s + 2 < NSTAGE) ldg_chunk(s + 2);
        __syncthreads();
    }

    if (tx == 0) {
#pragma unroll
        for (int t = 0; t < 4; t++) s_inds[(ty << 2) + t] = bidx[t];
    }
    __syncthreads();

    // gather z_q = emb[ind], write NCHW (coalesced), accumulate loss terms
    const int i  = tid & 63;
    const int cg = tid >> 6;                    // 0..3: c residue class
    const int ind = s_inds[i];
    const float* erow = emb + (size_t)ind * C_DIM;
    float lsq = 0.0f, llin = 0.0f;
    float* ob = out + ((size_t)b * C_DIM) * HW + s0 + i;
#pragma unroll 4
    for (int c2 = 0; c2 < 64; c2++) {
        int c = (c2 << 2) + cg;
        float q  = __ldg(erow + c);
        float zv = z_tile[c * TM + i];
        ob[(size_t)c * HW] = q;
        float dff = q - zv;
        lsq = fmaf(dff, dff, lsq);
        llin += dff;
    }
#pragma unroll
    for (int m = 16; m > 0; m >>= 1) {
        lsq  += __shfl_xor_sync(0xffffffffu, lsq, m);
        llin += __shfl_xor_sync(0xffffffffu, llin, m);
    }
    int wid = tid >> 5, lane = tid & 31;
    if (lane == 0) { s_red[wid] = lsq; s_red[8 + wid] = llin; }
    __syncthreads();
    if (tid == 0) {
        double a = 0.0, l = 0.0;
#pragma unroll
        for (int w = 0; w < 8; w++) { a += (double)s_red[w]; l += (double)s_red[8 + w]; }
        atomicAdd(&g_sumsq, a);
        atomicAdd(&g_sumlin, l);
    }
}

__global__ void vq_finalize_kernel(float* out, int nelem) {
    double m = (double)nelem;
    out[nelem] = (float)(g_sumsq / m + 0.25 * (g_sumlin / m));
}

// ---------------- launch ----------------
extern "C" void kernel_launch(void* const* d_in, const int* in_sizes, int n_in,
                              void* d_out, int out_size) {
    const float* z   = (const float*)d_in[0];   // [64,256,32,32]
    const float* emb = (const float*)d_in[1];   // [1024,256]
    float* out = (float*)d_out;                 // [64,256,32,32] ++ [loss]
    const int nelem = out_size - 1;             // 16777216

    cudaFuncSetAttribute(vq_main_kernel,
                         cudaFuncAttributeMaxDynamicSharedMemorySize, (int)SMEM_BYTES);

    vq_zero_kernel<<<1, 1>>>();
    vq_transpose_kernel<<<dim3(K_DIM / 32, C_DIM / 32), dim3(32, 8)>>>(emb);
    vq_esq_kernel<<<K_DIM / 8, 256>>>(emb);
    vq_zsq_kernel<<<(64 * HW) / 256, 256>>>(z);
    vq_main_kernel<<<(64 * HW) / TM, NTHREADS, SMEM_BYTES>>>(z, emb, out);
    vq_finalize_kernel<<<1, 1>>>(out, nelem);
}

// round 15
// speedup vs baseline: 2.8568x; 2.8568x over previous
#include <cuda_runtime.h>
#include <cstdint>

#define C_DIM 256
#define K_DIM 1024
#define HW    1024
#define TM    64
#define TN    128
#define CCH   32
#define NSTAGE 64         // 8 kc * 8 cc
#define NTHREADS 256

// ---------------- device globals (scratch; no runtime allocation) ----------------
__device__ __align__(16) float  g_embT[C_DIM * K_DIM];  // emb transposed: [c][k]
__device__ __align__(16) float  g_esq[K_DIM];           // ||e_k||^2 (ref fp32 bits)
__device__ __align__(16) float  g_zsq[64 * HW];         // ||z_n||^2 (ref fp32 bits)
__device__ double g_sumsq;
__device__ double g_sumlin;

// ---------------- tiny helper kernels ----------------
__global__ void vq_zero_kernel() { g_sumsq = 0.0; g_sumlin = 0.0; }

// emb [K][C] -> g_embT [C][K], classic 32x32 smem transpose
__global__ void vq_transpose_kernel(const float* __restrict__ emb) {
    __shared__ float t[32][33];
    int k0 = blockIdx.x * 32, c0 = blockIdx.y * 32;
    int tx = threadIdx.x, ty = threadIdx.y;
#pragma unroll
    for (int r = ty; r < 32; r += 8)
        t[r][tx] = emb[(size_t)(k0 + r) * C_DIM + c0 + tx];
    __syncthreads();
#pragma unroll
    for (int r = ty; r < 32; r += 8)
        g_embT[(size_t)(c0 + r) * K_DIM + k0 + tx] = t[tx][r];
}

// ||e_k||^2: warp loads row coalesced into smem, lane 0 does the bit-exact
// sequential fp32 reduce (mul/add separately rounded, c ascending).
__global__ void vq_esq_kernel(const float* __restrict__ emb) {
    __shared__ float row_s[8][C_DIM];
    int w = threadIdx.x >> 5, lane = threadIdx.x & 31;
    int k = blockIdx.x * 8 + w;
    const float* row = emb + (size_t)k * C_DIM;
#pragma unroll
    for (int r = 0; r < 8; r++) row_s[w][lane + 32 * r] = row[lane + 32 * r];
    __syncwarp();
    if (lane == 0) {
        float acc = 0.0f;
#pragma unroll 8
        for (int c = 0; c < C_DIM; c++) {
            float v = row_s[w][c];
            acc = __fadd_rn(acc, __fmul_rn(v, v));
        }
        g_esq[k] = acc;
    }
}

// ||z_n||^2: STRICT sequential fp32 over c ascending (coalesced across tokens)
__global__ void vq_zsq_kernel(const float* __restrict__ z) {
    int n = blockIdx.x * blockDim.x + threadIdx.x;
    int b = n >> 10, s = n & (HW - 1);
    const float* base = z + ((size_t)b * C_DIM) * HW + s;
    float acc = 0.0f;
#pragma unroll 8
    for (int c = 0; c < C_DIM; c++) {
        float v = base[(size_t)c * HW];
        acc = __fadd_rn(acc, __fmul_rn(v, v));
    }
    g_zsq[n] = acc;
}

// ---------------- packed f32x2 helpers ----------------
__device__ __forceinline__ unsigned long long splat2(float x) {
    unsigned long long r;
    unsigned int xi = __float_as_uint(x);
    asm("mov.b64 %0, {%1, %1};" : "=l"(r) : "r"(xi));
    return r;
}
__device__ __forceinline__ void fma2(unsigned long long& d,
                                     unsigned long long a,
                                     unsigned long long b) {
    asm("fma.rn.f32x2 %0, %1, %2, %0;" : "+l"(d) : "l"(a), "l"(b));
}
__device__ __forceinline__ void unpack2(unsigned long long v, float& lo, float& hi) {
    unsigned int l, h;
    asm("mov.b64 {%0, %1}, %2;" : "=r"(l), "=r"(h) : "l"(v));
    lo = __uint_as_float(l);
    hi = __uint_as_float(h);
}
// Emulate reference fp32 chain: d = fl( fl(zsq + esq) - fl(2*ez) )
__device__ __forceinline__ float ref_dist(float zsq, float esq, float ez) {
    float t = __fadd_rn(zsq, esq);
    return __fadd_rn(t, __fmul_rn(-2.0f, ez));
}

// ---------------- main kernel ----------------
// EXACT R5 inner loop (conflict-free LDS, splat MOVs) + double-buffered e
// staging with ONE sync per stage and LDG prefetch 2 stages ahead.
// R13 bug fixed: second code-group load is er+64 (code 64 of THIS c-row),
// not er+128 (next c-row).
// 64 tokens x 1024 codes per CTA, 256 thr, smem 96KB -> 2 CTAs/SM.
#define OFF_EBUF 65536u                       // z_tile: [256][64] fp32 = 64KB
#define OFF_INDS (OFF_EBUF + 2u * CCH * TN * 4u)   // ebuf: [2][32*128] = 32KB
#define OFF_RED  (OFF_INDS + 256u)
#define SMEM_BYTES (OFF_RED + 64u)

__global__ __launch_bounds__(NTHREADS, 2)
void vq_main_kernel(const float* __restrict__ z, const float* __restrict__ emb,
                    float* __restrict__ out) {
    extern __shared__ char smem[];
    float* z_tile = (float*)smem;                       // [256][64] c-major
    float* ebuf   = (float*)(smem + OFF_EBUF);          // [2][32][128] c-major
    int*   s_inds = (int*)(smem + OFF_INDS);            // [64]
    float* s_red  = (float*)(smem + OFF_RED);           // [16]

    const int tid = threadIdx.x;
    const int tx = tid & 15;   // code group (8 codes: tx*4..+3 and 64+tx*4..+3)
    const int ty = tid >> 4;   // token group (4 tokens: ty*4..+3)
    const int blk = blockIdx.x;
    const int b  = blk >> 4;
    const int s0 = (blk & 15) * TM;
    const float* zb = z + ((size_t)b * C_DIM) * HW + s0;

    // load z tile: z_tile[c][i] = z[b][c][s0+i] (fully coalesced)
#pragma unroll
    for (int r = 0; r < 16; r++) {
        int idx = tid + r * NTHREADS;
        int c = idx >> 4, i4 = idx & 15;
        *(float4*)&z_tile[c * TM + i4 * 4] =
            *(const float4*)(zb + (size_t)c * HW + i4 * 4);
    }

    float zs4[4];
#pragma unroll
    for (int t = 0; t < 4; t++)
        zs4[t] = g_zsq[b * HW + s0 + (ty << 2) + t];

    float bmin[4];
    int   bidx[4];
#pragma unroll
    for (int t = 0; t < 4; t++) { bmin[t] = 3.4e38f; bidx[t] = 0; }

    // ---- pipelined e staging: chunk = [32 c][128 codes] = 1024 float4s ----
    float4 rp[4];
    auto ldg_chunk = [&](int s) {
        int kc = s >> 3, cc = s & 7;
        const float* src = g_embT + (size_t)(cc * CCH) * K_DIM + kc * TN;
#pragma unroll
        for (int r = 0; r < 4; r++) {
            int idx = tid + r * NTHREADS;
            int c = idx >> 5, k4 = idx & 31;
            rp[r] = *(const float4*)(src + (size_t)c * K_DIM + k4 * 4);
        }
    };
    auto sts_chunk = [&](int buf) {
        float* dst = ebuf + (size_t)buf * (CCH * TN);
#pragma unroll
        for (int r = 0; r < 4; r++) {
            int idx = tid + r * NTHREADS;
            int c = idx >> 5, k4 = idx & 31;
            *(float4*)&dst[c * TN + k4 * 4] = rp[r];
        }
    };

    ldg_chunk(0);
    sts_chunk(0);
    ldg_chunk(1);
    __syncthreads();              // covers z_tile + ebuf[0]

    unsigned long long acc[4][4];

    for (int s = 0; s < NSTAGE; s++) {
        const int kc = s >> 3, cc = s & 7;
        if (cc == 0) {
#pragma unroll
            for (int t = 0; t < 4; t++)
#pragma unroll
                for (int p = 0; p < 4; p++) acc[t][p] = 0ull;
        }

        {   // ---- EXACT R5 inner loop on buf s&1 (32 c-iters) ----
            const float* zr = z_tile + (cc * CCH) * TM + (ty << 2);
            const float* er = ebuf + (size_t)(s & 1) * (CCH * TN) + (tx << 2);
#pragma unroll 8
            for (int cl = 0; cl < CCH; cl++) {
                float4 zz = *(const float4*)(zr);
                ulonglong2 eA = *(const ulonglong2*)(er);        // codes tx*4 .. +3
                ulonglong2 eB = *(const ulonglong2*)(er + 64);   // codes 64+tx*4 .. +3
                float zv[4] = {zz.x, zz.y, zz.z, zz.w};
                unsigned long long e0 = eA.x, e1 = eA.y, e2 = eB.x, e3 = eB.y;
#pragma unroll
                for (int t = 0; t < 4; t++) {
                    unsigned long long zs = splat2(zv[t]);
                    fma2(acc[t][0], zs, e0);   // fused-FMA chain over c ascending
                    fma2(acc[t][1], zs, e1);
                    fma2(acc[t][2], zs, e2);
                    fma2(acc[t][3], zs, e3);
                }
                zr += TM;
                er += TN;
            }
        }

        if (cc == 7) {   // kc epilogue: ref-emulated dist + running argmin (R5 verbatim)
            const int kA = kc * TN + (tx << 2);
            const int kB = kA + 64;
            float4 eqA = *(const float4*)&g_esq[kA];
            float4 eqB = *(const float4*)&g_esq[kB];
#pragma unroll
            for (int t = 0; t < 4; t++) {
                const float zs = zs4[t];
                float lo, hi;
                unpack2(acc[t][0], lo, hi);
                float da0 = ref_dist(zs, eqA.x, lo);
                float da1 = ref_dist(zs, eqA.y, hi);
                unpack2(acc[t][1], lo, hi);
                float da2 = ref_dist(zs, eqA.z, lo);
                float da3 = ref_dist(zs, eqA.w, hi);
                unpack2(acc[t][2], lo, hi);
                float db0 = ref_dist(zs, eqB.x, lo);
                float db1 = ref_dist(zs, eqB.y, hi);
                unpack2(acc[t][3], lo, hi);
                float db2 = ref_dist(zs, eqB.z, lo);
                float db3 = ref_dist(zs, eqB.w, hi);

                float bd = da0; int bk = kA;            // ascending k, strict <
                if (da1 < bd) { bd = da1; bk = kA + 1; }
                if (da2 < bd) { bd = da2; bk = kA + 2; }
                if (da3 < bd) { bd = da3; bk = kA + 3; }
                if (db0 < bd) { bd = db0; bk = kB;     }
                if (db1 < bd) { bd = db1; bk = kB + 1; }
                if (db2 < bd) { bd = db2; bk = kB + 2; }
                if (db3 < bd) { bd = db3; bk = kB + 3; }
#pragma unroll
                for (int m = 8; m > 0; m >>= 1) {       // reduce over 16 tx lanes
                    float od = __shfl_xor_sync(0xffffffffu, bd, m);
                    int   ok = __shfl_xor_sync(0xffffffffu, bk, m);
                    if (od < bd || (od == bd && ok < bk)) { bd = od; bk = ok; }
                }
                if (bd < bmin[t]) { bmin[t] = bd; bidx[t] = bk; }  // earlier kc wins ties
            }
        }

        // pipeline: store chunk s+1 (regs from last iter), prefetch chunk s+2
        if (s + 1 < NSTAGE) sts_chunk((s + 1) & 1);
        if (s + 2 < NSTAGE) ldg_chunk(s + 2);
        __syncthreads();
    }

    if (tx == 0) {
#pragma unroll
        for (int t = 0; t < 4; t++) s_inds[(ty << 2) + t] = bidx[t];
    }
    __syncthreads();

    // gather z_q = emb[ind], write NCHW (coalesced), accumulate loss terms
    const int i  = tid & 63;
    const int cg = tid >> 6;                    // 0..3: c residue class
    const int ind = s_inds[i];
    const float* erow = emb + (size_t)ind * C_DIM;
    float lsq = 0.0f, llin = 0.0f;
    float* ob = out + ((size_t)b * C_DIM) * HW + s0 + i;
#pragma unroll 4
    for (int c2 = 0; c2 < 64; c2++) {
        int c = (c2 << 2) + cg;
        float q  = __ldg(erow + c);
        float zv = z_tile[c * TM + i];
        ob[(size_t)c * HW] = q;
        float dff = q - zv;
        lsq = fmaf(dff, dff, lsq);
        llin += dff;
    }
#pragma unroll
    for (int m = 16; m > 0; m >>= 1) {
        lsq  += __shfl_xor_sync(0xffffffffu, lsq, m);
        llin += __shfl_xor_sync(0xffffffffu, llin, m);
    }
    int wid = tid >> 5, lane = tid & 31;
    if (lane == 0) { s_red[wid] = lsq; s_red[8 + wid] = llin; }
    __syncthreads();
    if (tid == 0) {
        double a = 0.0, l = 0.0;
#pragma unroll
        for (int w = 0; w < 8; w++) { a += (double)s_red[w]; l += (double)s_red[8 + w]; }
        atomicAdd(&g_sumsq, a);
        atomicAdd(&g_sumlin, l);
    }
}

__global__ void vq_finalize_kernel(float* out, int nelem) {
    double m = (double)nelem;
    out[nelem] = (float)(g_sumsq / m + 0.25 * (g_sumlin / m));
}

// ---------------- launch ----------------
extern "C" void kernel_launch(void* const* d_in, const int* in_sizes, int n_in,
                              void* d_out, int out_size) {
    const float* z   = (const float*)d_in[0];   // [64,256,32,32]
    const float* emb = (const float*)d_in[1];   // [1024,256]
    float* out = (float*)d_out;                 // [64,256,32,32] ++ [loss]
    const int nelem = out_size - 1;             // 16777216

    cudaFuncSetAttribute(vq_main_kernel,
                         cudaFuncAttributeMaxDynamicSharedMemorySize, (int)SMEM_BYTES);

    vq_zero_kernel<<<1, 1>>>();
    vq_transpose_kernel<<<dim3(K_DIM / 32, C_DIM / 32), dim3(32, 8)>>>(emb);
    vq_esq_kernel<<<K_DIM / 8, 256>>>(emb);
    vq_zsq_kernel<<<(64 * HW) / 256, 256>>>(z);
    vq_main_kernel<<<(64 * HW) / TM, NTHREADS, SMEM_BYTES>>>(z, emb, out);
    vq_finalize_kernel<<<1, 1>>>(out, nelem);
}

// round 17
// speedup vs baseline: 2.9227x; 1.0230x over previous
#include <cuda_runtime.h>
#include <cstdint>

#define C_DIM 256
#define K_DIM 1024
#define HW    1024
#define TM    64
#define TN    128
#define CCH   32
#define NSTAGE 64         // 8 kc * 8 cc
#define NTHREADS 256

// ---------------- device globals (scratch; no runtime allocation) ----------------
__device__ __align__(16) float  g_embT[C_DIM * K_DIM];  // emb transposed: [c][k]
__device__ __align__(16) float  g_esq[K_DIM];           // ||e_k||^2 (ref fp32 bits)
__device__ double g_sumsq;
__device__ double g_sumlin;

// ---------------- tiny helper kernels ----------------
__global__ void vq_zero_kernel() { g_sumsq = 0.0; g_sumlin = 0.0; }

// emb [K][C] -> g_embT [C][K], classic 32x32 smem transpose
__global__ void vq_transpose_kernel(const float* __restrict__ emb) {
    __shared__ float t[32][33];
    int k0 = blockIdx.x * 32, c0 = blockIdx.y * 32;
    int tx = threadIdx.x, ty = threadIdx.y;
#pragma unroll
    for (int r = ty; r < 32; r += 8)
        t[r][tx] = emb[(size_t)(k0 + r) * C_DIM + c0 + tx];
    __syncthreads();
#pragma unroll
    for (int r = ty; r < 32; r += 8)
        g_embT[(size_t)(c0 + r) * K_DIM + k0 + tx] = t[tx][r];
}

// ||e_k||^2: warp loads row coalesced into smem, lane 0 does the bit-exact
// sequential fp32 reduce (mul/add separately rounded, c ascending).
__global__ void vq_esq_kernel(const float* __restrict__ emb) {
    __shared__ float row_s[8][C_DIM];
    int w = threadIdx.x >> 5, lane = threadIdx.x & 31;
    int k = blockIdx.x * 8 + w;
    const float* row = emb + (size_t)k * C_DIM;
#pragma unroll
    for (int r = 0; r < 8; r++) row_s[w][lane + 32 * r] = row[lane + 32 * r];
    __syncwarp();
    if (lane == 0) {
        float acc = 0.0f;
#pragma unroll 8
        for (int c = 0; c < C_DIM; c++) {
            float v = row_s[w][c];
            acc = __fadd_rn(acc, __fmul_rn(v, v));
        }
        g_esq[k] = acc;
    }
}

// ---------------- packed f32x2 helpers ----------------
__device__ __forceinline__ unsigned long long splat2(float x) {
    unsigned long long r;
    unsigned int xi = __float_as_uint(x);
    asm("mov.b64 %0, {%1, %1};" : "=l"(r) : "r"(xi));
    return r;
}
__device__ __forceinline__ void fma2(unsigned long long& d,
                                     unsigned long long a,
                                     unsigned long long b) {
    asm("fma.rn.f32x2 %0, %1, %2, %0;" : "+l"(d) : "l"(a), "l"(b));
}
__device__ __forceinline__ void unpack2(unsigned long long v, float& lo, float& hi) {
    unsigned int l, h;
    asm("mov.b64 {%0, %1}, %2;" : "=r"(l), "=r"(h) : "l"(v));
    lo = __uint_as_float(l);
    hi = __uint_as_float(h);
}
// Emulate reference fp32 chain: d = fl( fl(zsq + esq) - fl(2*ez) )
__device__ __forceinline__ float ref_dist(float zsq, float esq, float ez) {
    float t = __fadd_rn(zsq, esq);
    return __fadd_rn(t, __fmul_rn(-2.0f, ez));
}

// ---------------- main kernel ----------------
// R15 (passing, at the FFMA2 RF-bank floor) + zsq FUSED: the standalone 24.5us
// DRAM re-read of z is replaced by a per-token sequential reduce over the
// already-staged z_tile (bit-identical op order: fadd(fmul), c ascending).
// 64 tokens x 1024 codes per CTA, 256 thr, smem 96KB -> 2 CTAs/SM.
#define OFF_EBUF 65536u                       // z_tile: [256][64] fp32 = 64KB
#define OFF_INDS (OFF_EBUF + 2u * CCH * TN * 4u)   // ebuf: [2][32*128] = 32KB
#define OFF_RED  (OFF_INDS + 256u)
#define SMEM_BYTES (OFF_RED + 64u)

__global__ __launch_bounds__(NTHREADS, 2)
void vq_main_kernel(const float* __restrict__ z, const float* __restrict__ emb,
                    float* __restrict__ out) {
    extern __shared__ char smem[];
    float* z_tile = (float*)smem;                       // [256][64] c-major
    float* ebuf   = (float*)(smem + OFF_EBUF);          // [2][32][128] c-major
    int*   s_inds = (int*)(smem + OFF_INDS);            // [64] (scratch: zsq, then inds)
    float* s_red  = (float*)(smem + OFF_RED);           // [16]

    const int tid = threadIdx.x;
    const int tx = tid & 15;   // code group (8 codes: tx*4..+3 and 64+tx*4..+3)
    const int ty = tid >> 4;   // token group (4 tokens: ty*4..+3)
    const int blk = blockIdx.x;
    const int b  = blk >> 4;
    const int s0 = (blk & 15) * TM;
    const float* zb = z + ((size_t)b * C_DIM) * HW + s0;

    // load z tile: z_tile[c][i] = z[b][c][s0+i] (fully coalesced)
#pragma unroll
    for (int r = 0; r < 16; r++) {
        int idx = tid + r * NTHREADS;
        int c = idx >> 4, i4 = idx & 15;
        *(float4*)&z_tile[c * TM + i4 * 4] =
            *(const float4*)(zb + (size_t)c * HW + i4 * 4);
    }

    // ---- pipelined e staging: chunk = [32 c][128 codes] = 1024 float4s ----
    float4 rp[4];
    auto ldg_chunk = [&](int s) {
        int kc = s >> 3, cc = s & 7;
        const float* src = g_embT + (size_t)(cc * CCH) * K_DIM + kc * TN;
#pragma unroll
        for (int r = 0; r < 4; r++) {
            int idx = tid + r * NTHREADS;
            int c = idx >> 5, k4 = idx & 31;
            rp[r] = *(const float4*)(src + (size_t)c * K_DIM + k4 * 4);
        }
    };
    auto sts_chunk = [&](int buf) {
        float* dst = ebuf + (size_t)buf * (CCH * TN);
#pragma unroll
        for (int r = 0; r < 4; r++) {
            int idx = tid + r * NTHREADS;
            int c = idx >> 5, k4 = idx & 31;
            *(float4*)&dst[c * TN + k4 * 4] = rp[r];
        }
    };

    ldg_chunk(0);
    sts_chunk(0);
    ldg_chunk(1);
    __syncthreads();              // z_tile + ebuf[0] visible

    // ---- fused zsq: threads 0..63 run the reference's sequential fp32 chain
    //      over their token's column (identical bits to the old vq_zsq kernel)
    float* szsq = (float*)s_inds;             // scratch overlay (64 floats)
    if (tid < TM) {
        float acc = 0.0f;
#pragma unroll 8
        for (int c = 0; c < C_DIM; c++) {
            float v = z_tile[c * TM + tid];
            acc = __fadd_rn(acc, __fmul_rn(v, v));
        }
        szsq[tid] = acc;
    }
    __syncthreads();

    float zs4[4];
#pragma unroll
    for (int t = 0; t < 4; t++)
        zs4[t] = szsq[(ty << 2) + t];

    float bmin[4];
    int   bidx[4];
#pragma unroll
    for (int t = 0; t < 4; t++) { bmin[t] = 3.4e38f; bidx[t] = 0; }

    unsigned long long acc[4][4];

    for (int s = 0; s < NSTAGE; s++) {
        const int kc = s >> 3, cc = s & 7;
        if (cc == 0) {
#pragma unroll
            for (int t = 0; t < 4; t++)
#pragma unroll
                for (int p = 0; p < 4; p++) acc[t][p] = 0ull;
        }

        {   // ---- R5 inner loop on buf s&1 (32 c-iters) ----
            const float* zr = z_tile + (cc * CCH) * TM + (ty << 2);
            const float* er = ebuf + (size_t)(s & 1) * (CCH * TN) + (tx << 2);
#pragma unroll 8
            for (int cl = 0; cl < CCH; cl++) {
                float4 zz = *(const float4*)(zr);
                ulonglong2 eA = *(const ulonglong2*)(er);        // codes tx*4 .. +3
                ulonglong2 eB = *(const ulonglong2*)(er + 64);   // codes 64+tx*4 .. +3
                float zv[4] = {zz.x, zz.y, zz.z, zz.w};
                unsigned long long e0 = eA.x, e1 = eA.y, e2 = eB.x, e3 = eB.y;
#pragma unroll
                for (int t = 0; t < 4; t++) {
                    unsigned long long zs = splat2(zv[t]);
                    fma2(acc[t][0], zs, e0);   // fused-FMA chain over c ascending
                    fma2(acc[t][1], zs, e1);
                    fma2(acc[t][2], zs, e2);
                    fma2(acc[t][3], zs, e3);
                }
                zr += TM;
                er += TN;
            }
        }

        if (cc == 7) {   // kc epilogue: ref-emulated dist + running argmin
            const int kA = kc * TN + (tx << 2);
            const int kB = kA + 64;
            float4 eqA = *(const float4*)&g_esq[kA];
            float4 eqB = *(const float4*)&g_esq[kB];
#pragma unroll
            for (int t = 0; t < 4; t++) {
                const float zs = zs4[t];
                float lo, hi;
                unpack2(acc[t][0], lo, hi);
                float da0 = ref_dist(zs, eqA.x, lo);
                float da1 = ref_dist(zs, eqA.y, hi);
                unpack2(acc[t][1], lo, hi);
                float da2 = ref_dist(zs, eqA.z, lo);
                float da3 = ref_dist(zs, eqA.w, hi);
                unpack2(acc[t][2], lo, hi);
                float db0 = ref_dist(zs, eqB.x, lo);
                float db1 = ref_dist(zs, eqB.y, hi);
                unpack2(acc[t][3], lo, hi);
                float db2 = ref_dist(zs, eqB.z, lo);
                float db3 = ref_dist(zs, eqB.w, hi);

                float bd = da0; int bk = kA;            // ascending k, strict <
                if (da1 < bd) { bd = da1; bk = kA + 1; }
                if (da2 < bd) { bd = da2; bk = kA + 2; }
                if (da3 < bd) { bd = da3; bk = kA + 3; }
                if (db0 < bd) { bd = db0; bk = kB;     }
                if (db1 < bd) { bd = db1; bk = kB + 1; }
                if (db2 < bd) { bd = db2; bk = kB + 2; }
                if (db3 < bd) { bd = db3; bk = kB + 3; }
#pragma unroll
                for (int m = 8; m > 0; m >>= 1) {       // reduce over 16 tx lanes
                    float od = __shfl_xor_sync(0xffffffffu, bd, m);
                    int   ok = __shfl_xor_sync(0xffffffffu, bk, m);
                    if (od < bd || (od == bd && ok < bk)) { bd = od; bk = ok; }
                }
                if (bd < bmin[t]) { bmin[t] = bd; bidx[t] = bk; }  // earlier kc wins ties
            }
        }

        // pipeline: store chunk s+1 (regs from last iter), prefetch chunk s+2
        if (s + 1 < NSTAGE) sts_chunk((s + 1) & 1);
        if (s + 2 < NSTAGE) ldg_chunk(s + 2);
        __syncthreads();
    }

    if (tx == 0) {
#pragma unroll
        for (int t = 0; t < 4; t++) s_inds[(ty << 2) + t] = bidx[t];
    }
    __syncthreads();

    // gather z_q = emb[ind], write NCHW (coalesced), accumulate loss terms
    const int i  = tid & 63;
    const int cg = tid >> 6;                    // 0..3: c residue class
    const int ind = s_inds[i];
    const float* erow = emb + (size_t)ind * C_DIM;
    float lsq = 0.0f, llin = 0.0f;
    float* ob = out + ((size_t)b * C_DIM) * HW + s0 + i;
#pragma unroll 4
    for (int c2 = 0; c2 < 64; c2++) {
        int c = (c2 << 2) + cg;
        float q  = __ldg(erow + c);
        float zv = z_tile[c * TM + i];
        ob[(size_t)c * HW] = q;
        float dff = q - zv;
        lsq = fmaf(dff, dff, lsq);
        llin += dff;
    }
#pragma unroll
    for (int m = 16; m > 0; m >>= 1) {
        lsq  += __shfl_xor_sync(0xffffffffu, lsq, m);
        llin += __shfl_xor_sync(0xffffffffu, llin, m);
    }
    int wid = tid >> 5, lane = tid & 31;
    if (lane == 0) { s_red[wid] = lsq; s_red[8 + wid] = llin; }
    __syncthreads();
    if (tid == 0) {
        double a = 0.0, l = 0.0;
#pragma unroll
        for (int w = 0; w < 8; w++) { a += (double)s_red[w]; l += (double)s_red[8 + w]; }
        atomicAdd(&g_sumsq, a);
        atomicAdd(&g_sumlin, l);
    }
}

__global__ void vq_finalize_kernel(float* out, int nelem) {
    double m = (double)nelem;
    out[nelem] = (float)(g_sumsq / m + 0.25 * (g_sumlin / m));
}

// ---------------- launch ----------------
extern "C" void kernel_launch(void* const* d_in, const int* in_sizes, int n_in,
                              void* d_out, int out_size) {
    const float* z   = (const float*)d_in[0];   // [64,256,32,32]
    const float* emb = (const float*)d_in[1];   // [1024,256]
    float* out = (float*)d_out;                 // [64,256,32,32] ++ [loss]
    const int nelem = out_size - 1;             // 16777216

    cudaFuncSetAttribute(vq_main_kernel,
                         cudaFuncAttributeMaxDynamicSharedMemorySize, (int)SMEM_BYTES);

    vq_zero_kernel<<<1, 1>>>();
    vq_transpose_kernel<<<dim3(K_DIM / 32, C_DIM / 32), dim3(32, 8)>>>(emb);
    vq_esq_kernel<<<K_DIM / 8, 256>>>(emb);
    vq_main_kernel<<<(64 * HW) / TM, NTHREADS, SMEM_BYTES>>>(z, emb, out);
    vq_finalize_kernel<<<1, 1>>>(out, nelem);
}